// round 5
// baseline (speedup 1.0000x reference)
#include <cuda_runtime.h>

// LRF_11330123727115
// Inputs : d_in[0] = neighbor (B=64, G=2048, S=64, C=3) float32 (center unused)
// Output : d_out = [ rot_neighbor (B,G,S,3) | lrfs (B,G,3,3) ] float32
//
// One warp per group. Eigenvectors of the 3x3 weighted covariance are computed
// by a faithful fp32 emulation of LAPACK ssyevd (ssytd2 + ssteqr + sormtr) so
// that eigenvector SIGNS match jnp.linalg.eigh on CPU. This matters because the
// direction-disambiguation step has a tie at n_pos==32 (P ~ 9.9% per axis) where
// the reference output inherits eigh's arbitrary sign.

constexpr int NG = 64 * 2048;   // 131072 groups
constexpr long long ROT_ELEMS = (long long)NG * 64 * 3;

// ---------------- LAPACK helper emulations (fp32, IEEE ops) ----------------

__device__ __forceinline__ float f_slapy2(float x, float y) {
    float ax = fabsf(x), ay = fabsf(y);
    float w = fmaxf(ax, ay), z = fminf(ax, ay);
    if (z == 0.f) return w;
    float q = __fdiv_rn(z, w);
    return w * __fsqrt_rn(1.f + q * q);
}

// LAPACK >= 3.10 slartg: r = sign(f)*sqrt(f^2+g^2), c = |f|/|r| >= 0, s = g/r
__device__ __forceinline__ void f_slartg(float f, float g, float& c, float& s, float& r) {
    if (g == 0.f)      { c = 1.f; s = 0.f; r = f; }
    else if (f == 0.f) { c = 0.f; s = copysignf(1.f, g); r = fabsf(g); }
    else {
        float d = __fsqrt_rn(f * f + g * g);
        c = __fdiv_rn(fabsf(f), d);
        r = copysignf(d, f);
        s = __fdiv_rn(g, r);
    }
}

__device__ __forceinline__ void f_slaev2(float a, float b, float c,
                                         float& rt1, float& rt2,
                                         float& cs1, float& sn1) {
    float sm = a + c, df = a - c;
    float adf = fabsf(df), tb = b + b, ab = fabsf(tb);
    float acmx, acmn;
    if (fabsf(a) > fabsf(c)) { acmx = a; acmn = c; } else { acmx = c; acmn = a; }
    float rt;
    if (adf > ab)      { float q = __fdiv_rn(ab, adf); rt = adf * __fsqrt_rn(1.f + q * q); }
    else if (adf < ab) { float q = __fdiv_rn(adf, ab); rt = ab * __fsqrt_rn(1.f + q * q); }
    else               rt = ab * __fsqrt_rn(2.f);
    int sgn1;
    if (sm < 0.f) {
        rt1 = 0.5f * (sm - rt); sgn1 = -1;
        rt2 = __fdiv_rn(acmx, rt1) * acmn - __fdiv_rn(b, rt1) * b;
    } else if (sm > 0.f) {
        rt1 = 0.5f * (sm + rt); sgn1 = 1;
        rt2 = __fdiv_rn(acmx, rt1) * acmn - __fdiv_rn(b, rt1) * b;
    } else {
        rt1 = 0.5f * rt; rt2 = -0.5f * rt; sgn1 = 1;
    }
    int sgn2; float cs;
    if (df >= 0.f) { cs = df + rt; sgn2 = 1; }
    else           { cs = df - rt; sgn2 = -1; }
    float acs = fabsf(cs);
    if (acs > ab) {
        float ct = __fdiv_rn(-tb, cs);
        sn1 = __fdiv_rn(1.f, __fsqrt_rn(1.f + ct * ct));
        cs1 = ct * sn1;
    } else if (ab == 0.f) {
        cs1 = 1.f; sn1 = 0.f;
    } else {
        float tn = __fdiv_rn(-cs, tb);
        cs1 = __fdiv_rn(1.f, __fsqrt_rn(1.f + tn * tn));
        sn1 = tn * cs1;
    }
    if (sgn1 == sgn2) { float tn = cs1; cs1 = -sn1; sn1 = tn; }
}

// ssyevd(n=3, uplo='L') emulation: ssytd2 -> ssteqr('I') -> sort -> sormtr.
// Cpk packed lower: [c00, c10, c20, c11, c21, c22]
__device__ void eigh3_lapack(const float Cpk[6], float zv[3], float xv[3]) {
    float a11 = Cpk[0], a21 = Cpk[1], a31 = Cpk[2];
    float a22 = Cpk[3], a32 = Cpk[4], a33 = Cpk[5];

    // ---- ssytd2 lower: one reflector annihilating a31 ----
    float d[3], e[2], tau1, v3;
    {
        float xnorm = fabsf(a31);
        if (xnorm == 0.f) { tau1 = 0.f; v3 = 0.f; e[0] = a21; }
        else {
            float beta = -copysignf(f_slapy2(a21, xnorm), a21);
            tau1 = __fdiv_rn(beta - a21, beta);
            v3 = a31 * __fdiv_rn(1.f, a21 - beta);
            e[0] = beta;
        }
        if (tau1 != 0.f) {
            float x1 = tau1 * (a22 + a32 * v3);   // x = tau*A22*v, v=[1,v3]
            float x2 = tau1 * (a32 + a33 * v3);
            float al = -0.5f * tau1 * (x1 + x2 * v3);
            float w1 = x1 + al;
            float w2 = x2 + al * v3;
            a22 = a22 - w1 - w1;                  // A -= v w^T + w v^T
            a32 = a32 - v3 * w1 - w2;
            a33 = a33 - v3 * w2 - v3 * w2;
        }
        d[0] = a11; d[1] = a22; d[2] = a33; e[1] = a32;
    }

    // ---- ssteqr('I', n=3) ----
    float Z[3][3] = {{1.f,0.f,0.f},{0.f,1.f,0.f},{0.f,0.f,1.f}};
    const float eps    = 5.9604645e-08f;   // slamch('E') for IEEE single
    const float eps2   = eps * eps;
    const float safmin = 1.1754944e-38f;
    const int   nmaxit = 90;               // 3 * 30
    int jtot = 0, l1 = 1;
    float wc[2], ws[2];

    for (;;) {                                       // label 10
        if (l1 > 3) break;
        if (l1 > 1) e[l1 - 2] = 0.f;
        int m = 3;
        if (l1 <= 2) {
            for (int mm = l1; mm <= 2; mm++) {
                float tst = fabsf(e[mm - 1]);
                if (tst == 0.f) { m = mm; break; }
                if (tst <= (__fsqrt_rn(fabsf(d[mm - 1])) *
                            __fsqrt_rn(fabsf(d[mm]))) * eps) {
                    e[mm - 1] = 0.f; m = mm; break;
                }
            }
        }
        int l = l1, lsv = l, lend = m, lendsv = lend;
        l1 = m + 1;
        if (lend == l) continue;
        float anorm = 0.f;
        for (int i = l; i <= lend; i++)     anorm = fmaxf(anorm, fabsf(d[i - 1]));
        for (int i = l; i <= lend - 1; i++) anorm = fmaxf(anorm, fabsf(e[i - 1]));
        if (anorm == 0.f) continue;
        if (fabsf(d[lend - 1]) < fabsf(d[l - 1])) { lend = lsv; l = lendsv; }

        if (lend > l) {
            // ================= QL iteration =================
            for (;;) {                                // label 40
                int m2 = lend;
                if (l != lend) {
                    for (int mm = l; mm <= lend - 1; mm++) {
                        float tst = e[mm - 1] * e[mm - 1];
                        if (tst <= (eps2 * fabsf(d[mm - 1])) * fabsf(d[mm]) + safmin) {
                            m2 = mm; break;
                        }
                    }
                }
                if (m2 < lend) e[m2 - 1] = 0.f;
                float p = d[l - 1];
                if (m2 == l) {                        // eigenvalue found
                    d[l - 1] = p; l++;
                    if (l <= lend) continue;
                    break;
                }
                if (m2 == l + 1) {                    // 2x2 deflation
                    float rt1, rt2, c2, s2;
                    f_slaev2(d[l - 1], e[l - 1], d[l], rt1, rt2, c2, s2);
                    #pragma unroll
                    for (int i = 0; i < 3; i++) {     // slasr 'R','V','B', 2 cols (l,l+1)
                        float t = Z[i][l];
                        Z[i][l]     = c2 * t - s2 * Z[i][l - 1];
                        Z[i][l - 1] = s2 * t + c2 * Z[i][l - 1];
                    }
                    d[l - 1] = rt1; d[l] = rt2; e[l - 1] = 0.f;
                    l += 2;
                    if (l <= lend) continue;
                    break;
                }
                if (jtot == nmaxit) break;
                jtot++;
                float g = __fdiv_rn(d[l] - p, 2.f * e[l - 1]);
                float r = f_slapy2(g, 1.f);
                g = d[m2 - 1] - p + __fdiv_rn(e[l - 1], g + copysignf(r, g));
                float sv = 1.f, cv = 1.f;
                p = 0.f;
                for (int i = m2 - 1; i >= l; i--) {
                    float f = sv * e[i - 1];
                    float b = cv * e[i - 1];
                    f_slartg(g, f, cv, sv, r);
                    if (i != m2 - 1) e[i] = r;
                    g = d[i] - p;
                    r = (d[i - 1] - g) * sv + 2.f * cv * b;
                    p = sv * r;
                    d[i] = g + p;
                    g = cv * r - b;
                    wc[i - 1] = cv; ws[i - 1] = -sv;
                }
                int mm = m2 - l + 1;                  // slasr 'R','V','B'
                for (int j = mm - 1; j >= 1; j--) {
                    float cc = wc[l + j - 2], ssv = ws[l + j - 2];
                    #pragma unroll
                    for (int i = 0; i < 3; i++) {
                        float t = Z[i][l + j - 1];
                        Z[i][l + j - 1] = cc * t - ssv * Z[i][l + j - 2];
                        Z[i][l + j - 2] = ssv * t + cc * Z[i][l + j - 2];
                    }
                }
                d[l - 1] -= p;
                e[l - 1] = g;
            }
        } else {
            // ================= QR iteration =================
            for (;;) {                                // label 90
                int m2 = lend;
                if (l != lend) {
                    for (int mm = l; mm >= lend + 1; mm--) {
                        float tst = e[mm - 2] * e[mm - 2];
                        if (tst <= (eps2 * fabsf(d[mm - 1])) * fabsf(d[mm - 2]) + safmin) {
                            m2 = mm; break;
                        }
                    }
                }
                if (m2 > lend) e[m2 - 2] = 0.f;
                float p = d[l - 1];
                if (m2 == l) {
                    d[l - 1] = p; l--;
                    if (l >= lend) continue;
                    break;
                }
                if (m2 == l - 1) {
                    float rt1, rt2, c2, s2;
                    f_slaev2(d[l - 2], e[l - 2], d[l - 1], rt1, rt2, c2, s2);
                    #pragma unroll
                    for (int i = 0; i < 3; i++) {     // slasr 'R','V','F', 2 cols (l-1,l)
                        float t = Z[i][l - 1];
                        Z[i][l - 1] = c2 * t - s2 * Z[i][l - 2];
                        Z[i][l - 2] = s2 * t + c2 * Z[i][l - 2];
                    }
                    d[l - 2] = rt1; d[l - 1] = rt2; e[l - 2] = 0.f;
                    l -= 2;
                    if (l >= lend) continue;
                    break;
                }
                if (jtot == nmaxit) break;
                jtot++;
                float g = __fdiv_rn(d[l - 2] - p, 2.f * e[l - 2]);
                float r = f_slapy2(g, 1.f);
                g = d[m2 - 1] - p + __fdiv_rn(e[l - 2], g + copysignf(r, g));
                float sv = 1.f, cv = 1.f;
                p = 0.f;
                for (int i = m2; i <= l - 1; i++) {
                    float f = sv * e[i - 1];
                    float b = cv * e[i - 1];
                    f_slartg(g, f, cv, sv, r);
                    if (i != m2) e[i - 2] = r;
                    g = d[i - 1] - p;
                    r = (d[i] - g) * sv + 2.f * cv * b;
                    p = sv * r;
                    d[i - 1] = g + p;
                    g = cv * r - b;
                    wc[i - 1] = cv; ws[i - 1] = sv;
                }
                int mm = l - m2 + 1;                  // slasr 'R','V','F'
                for (int j = 1; j <= mm - 1; j++) {
                    float cc = wc[m2 + j - 2], ssv = ws[m2 + j - 2];
                    #pragma unroll
                    for (int i = 0; i < 3; i++) {
                        float t = Z[i][m2 + j - 1];
                        Z[i][m2 + j - 1] = cc * t - ssv * Z[i][m2 + j - 2];
                        Z[i][m2 + j - 2] = ssv * t + cc * Z[i][m2 + j - 2];
                    }
                }
                d[l - 1] -= p;
                e[l - 2] = g;
            }
        }
    }

    // ---- selection sort ascending (LAPACK convention: min swaps) ----
    for (int ii = 2; ii <= 3; ii++) {
        int i = ii - 1, k = i;
        float p = d[i - 1];
        for (int j = ii; j <= 3; j++)
            if (d[j - 1] < p) { k = j; p = d[j - 1]; }
        if (k != i) {
            d[k - 1] = d[i - 1]; d[i - 1] = p;
            #pragma unroll
            for (int r2 = 0; r2 < 3; r2++) {
                float t = Z[r2][i - 1]; Z[r2][i - 1] = Z[r2][k - 1]; Z[r2][k - 1] = t;
            }
        }
    }

    // ---- sormtr: Z = H1 * Z (H1 acts on rows 1,2) ----
    if (tau1 != 0.f) {
        #pragma unroll
        for (int j = 0; j < 3; j++) {
            float t = Z[1][j] + v3 * Z[2][j];
            Z[1][j] -= tau1 * t;
            Z[2][j] -= tau1 * v3 * t;
        }
    }

    zv[0] = Z[0][0]; zv[1] = Z[1][0]; zv[2] = Z[2][0];   // smallest eigval
    xv[0] = Z[0][2]; xv[1] = Z[1][2]; xv[2] = Z[2][2];   // largest eigval
}

// ------------------------------- main kernel -------------------------------

__global__ __launch_bounds__(256, 1) void lrf_kernel(
    const float* __restrict__ nb, float* __restrict__ out)
{
    const int wib  = threadIdx.x >> 5;
    const int lane = threadIdx.x & 31;
    const int g    = blockIdx.x * 8 + wib;

    __shared__ float sm[8][192];

    // coalesced load of the group's 64x3 floats
    const float* src = nb + (size_t)g * 192;
    #pragma unroll
    for (int k = 0; k < 6; k++)
        sm[wib][lane + 32 * k] = src[lane + 32 * k];
    __syncwarp();

    const int o = lane * 6;   // two points per lane
    const float p0x = sm[wib][o + 0], p0y = sm[wib][o + 1], p0z = sm[wib][o + 2];
    const float p1x = sm[wib][o + 3], p1y = sm[wib][o + 4], p1z = sm[wib][o + 5];

    // weights exactly as reference: w = (max_norm - norm) / (sum + 1e-6)
    const float n0 = __fsqrt_rn(p0x * p0x + p0y * p0y + p0z * p0z);
    const float n1 = __fsqrt_rn(p1x * p1x + p1y * p1y + p1z * p1z);
    float mx = fmaxf(n0, n1);
    #pragma unroll
    for (int dd = 16; dd; dd >>= 1)
        mx = fmaxf(mx, __shfl_xor_sync(0xffffffffu, mx, dd));
    const float w0 = mx - n0, w1 = mx - n1;
    float swt = w0 + w1;
    #pragma unroll
    for (int dd = 16; dd; dd >>= 1)
        swt += __shfl_xor_sync(0xffffffffu, swt, dd);
    const float denom = swt + 1e-6f;
    const float q0 = __fdiv_rn(w0, denom);
    const float q1 = __fdiv_rn(w1, denom);

    // covariance over scaled_pos = 100*pos, term = (w*sp_k)*sp_l
    const float s0x = 100.f * p0x, s0y = 100.f * p0y, s0z = 100.f * p0z;
    const float s1x = 100.f * p1x, s1y = 100.f * p1y, s1z = 100.f * p1z;
    float cxx = (q0 * s0x) * s0x + (q1 * s1x) * s1x;
    float cxy = (q0 * s0y) * s0x + (q1 * s1y) * s1x;   // C[1][0]
    float cxz = (q0 * s0z) * s0x + (q1 * s1z) * s1x;   // C[2][0]
    float cyy = (q0 * s0y) * s0y + (q1 * s1y) * s1y;
    float cyz = (q0 * s0z) * s0y + (q1 * s1z) * s1y;   // C[2][1]
    float czz = (q0 * s0z) * s0z + (q1 * s1z) * s1z;
    #pragma unroll
    for (int dd = 16; dd; dd >>= 1) {
        cxx += __shfl_xor_sync(0xffffffffu, cxx, dd);
        cxy += __shfl_xor_sync(0xffffffffu, cxy, dd);
        cxz += __shfl_xor_sync(0xffffffffu, cxz, dd);
        cyy += __shfl_xor_sync(0xffffffffu, cyy, dd);
        cyz += __shfl_xor_sync(0xffffffffu, cyz, dd);
        czz += __shfl_xor_sync(0xffffffffu, czz, dd);
    }

    // LAPACK-faithful eigensolve on lane 0 only (local arrays -> 32x less LDL/STL)
    float zx = 0.f, zy = 0.f, zz = 0.f, xx = 0.f, xy = 0.f, xz = 0.f;
    if (lane == 0) {
        float Cpk[6] = {cxx, cxy, cxz, cyy, cyz, czz};
        float zv[3], xv[3];
        eigh3_lapack(Cpk, zv, xv);
        zx = zv[0]; zy = zv[1]; zz = zv[2];
        xx = xv[0]; xy = xv[1]; xz = xv[2];
    }
    zx = __shfl_sync(0xffffffffu, zx, 0);
    zy = __shfl_sync(0xffffffffu, zy, 0);
    zz = __shfl_sync(0xffffffffu, zz, 0);
    xx = __shfl_sync(0xffffffffu, xx, 0);
    xy = __shfl_sync(0xffffffffu, xy, 0);
    xz = __shfl_sync(0xffffffffu, xz, 0);

    // disambiguate: flip if #(pos . v > 0) < 32 ; tie keeps eigh's sign
    {
        float pj0 = zx * p0x + zy * p0y + zz * p0z;
        float pj1 = zx * p1x + zy * p1y + zz * p1z;
        int npos = __popc(__ballot_sync(0xffffffffu, pj0 > 0.f)) +
                   __popc(__ballot_sync(0xffffffffu, pj1 > 0.f));
        if (npos < 32) { zx = -zx; zy = -zy; zz = -zz; }
    }
    {
        float pj0 = xx * p0x + xy * p0y + xz * p0z;
        float pj1 = xx * p1x + xy * p1y + xz * p1z;
        int npos = __popc(__ballot_sync(0xffffffffu, pj0 > 0.f)) +
                   __popc(__ballot_sync(0xffffffffu, pj1 > 0.f));
        if (npos < 32) { xx = -xx; xy = -xy; xz = -xz; }
    }

    // y = z x x
    const float yx = zy * xz - zz * xy;
    const float yy = zz * xx - zx * xz;
    const float yz = zx * xy - zy * xx;

    // lrfs: rows = component, cols = (z, y, x)
    if (lane == 0) {
        float* L = out + ROT_ELEMS + (size_t)g * 9;
        L[0] = zx; L[1] = yx; L[2] = xx;
        L[3] = zy; L[4] = yy; L[5] = xy;
        L[6] = zz; L[7] = yz; L[8] = xz;
    }

    // rot_neighbor = pos @ lrfs, staged through smem for coalesced stores
    __syncwarp();
    sm[wib][o + 0] = p0x * zx + p0y * zy + p0z * zz;
    sm[wib][o + 1] = p0x * yx + p0y * yy + p0z * yz;
    sm[wib][o + 2] = p0x * xx + p0y * xy + p0z * xz;
    sm[wib][o + 3] = p1x * zx + p1y * zy + p1z * zz;
    sm[wib][o + 4] = p1x * yx + p1y * yy + p1z * yz;
    sm[wib][o + 5] = p1x * xx + p1y * xy + p1z * xz;
    __syncwarp();

    float* dst = out + (size_t)g * 192;
    #pragma unroll
    for (int k = 0; k < 6; k++)
        dst[lane + 32 * k] = sm[wib][lane + 32 * k];
}

extern "C" void kernel_launch(void* const* d_in, const int* in_sizes, int n_in,
                              void* d_out, int out_size) {
    const float* neighbor = (const float*)d_in[0];
    float* out = (float*)d_out;
    lrf_kernel<<<NG / 8, 256>>>(neighbor, out);
}

// round 6
// speedup vs baseline: 2.3391x; 2.3391x over previous
#include <cuda_runtime.h>

// LRF_11330123727115
// Inputs : d_in[0] = neighbor (B=64, G=2048, S=64, C=3) float32 (center unused)
// Output : d_out = [ rot_neighbor (B,G,S,3) | lrfs (B,G,3,3) ] float32
//
// Block of 256 threads owns 32 groups. Per-warp (4 groups each): coalesced
// load + covariance butterfly reduction. Then warp 0's 32 LANES each run the
// LAPACK-faithful (ssytd2+ssteqr+sormtr fp32) eigensolver for one group —
// this removes the R5 bottleneck where every warp issued the whole eigensolve
// with 31/32 lanes masked (issue-bound at 278us, DRAM 8%). The eigensolve
// bitstream is unchanged, so eigenvector SIGNS still match jnp.linalg.eigh
// (needed for the n_pos==32 disambiguation ties, ~9.9%/axis).

constexpr int NG = 64 * 2048;   // 131072 groups
constexpr long long ROT_ELEMS = (long long)NG * 64 * 3;

// ---------------- LAPACK helper emulations (fp32, IEEE ops) ----------------

__device__ __forceinline__ float f_slapy2(float x, float y) {
    float ax = fabsf(x), ay = fabsf(y);
    float w = fmaxf(ax, ay), z = fminf(ax, ay);
    if (z == 0.f) return w;
    float q = __fdiv_rn(z, w);
    return w * __fsqrt_rn(1.f + q * q);
}

// LAPACK >= 3.10 slartg: r = sign(f)*sqrt(f^2+g^2), c = |f|/|r| >= 0, s = g/r
__device__ __forceinline__ void f_slartg(float f, float g, float& c, float& s, float& r) {
    if (g == 0.f)      { c = 1.f; s = 0.f; r = f; }
    else if (f == 0.f) { c = 0.f; s = copysignf(1.f, g); r = fabsf(g); }
    else {
        float d = __fsqrt_rn(f * f + g * g);
        c = __fdiv_rn(fabsf(f), d);
        r = copysignf(d, f);
        s = __fdiv_rn(g, r);
    }
}

__device__ __forceinline__ void f_slaev2(float a, float b, float c,
                                         float& rt1, float& rt2,
                                         float& cs1, float& sn1) {
    float sm = a + c, df = a - c;
    float adf = fabsf(df), tb = b + b, ab = fabsf(tb);
    float acmx, acmn;
    if (fabsf(a) > fabsf(c)) { acmx = a; acmn = c; } else { acmx = c; acmn = a; }
    float rt;
    if (adf > ab)      { float q = __fdiv_rn(ab, adf); rt = adf * __fsqrt_rn(1.f + q * q); }
    else if (adf < ab) { float q = __fdiv_rn(adf, ab); rt = ab * __fsqrt_rn(1.f + q * q); }
    else               rt = ab * __fsqrt_rn(2.f);
    int sgn1;
    if (sm < 0.f) {
        rt1 = 0.5f * (sm - rt); sgn1 = -1;
        rt2 = __fdiv_rn(acmx, rt1) * acmn - __fdiv_rn(b, rt1) * b;
    } else if (sm > 0.f) {
        rt1 = 0.5f * (sm + rt); sgn1 = 1;
        rt2 = __fdiv_rn(acmx, rt1) * acmn - __fdiv_rn(b, rt1) * b;
    } else {
        rt1 = 0.5f * rt; rt2 = -0.5f * rt; sgn1 = 1;
    }
    int sgn2; float cs;
    if (df >= 0.f) { cs = df + rt; sgn2 = 1; }
    else           { cs = df - rt; sgn2 = -1; }
    float acs = fabsf(cs);
    if (acs > ab) {
        float ct = __fdiv_rn(-tb, cs);
        sn1 = __fdiv_rn(1.f, __fsqrt_rn(1.f + ct * ct));
        cs1 = ct * sn1;
    } else if (ab == 0.f) {
        cs1 = 1.f; sn1 = 0.f;
    } else {
        float tn = __fdiv_rn(-cs, tb);
        cs1 = __fdiv_rn(1.f, __fsqrt_rn(1.f + tn * tn));
        sn1 = tn * cs1;
    }
    if (sgn1 == sgn2) { float tn = cs1; cs1 = -sn1; sn1 = tn; }
}

// ssyevd(n=3, uplo='L') emulation: ssytd2 -> ssteqr('I') -> sort -> sormtr.
// Cpk packed lower: [c00, c10, c20, c11, c21, c22]
__device__ void eigh3_lapack(const float Cpk[6], float zv[3], float xv[3]) {
    float a11 = Cpk[0], a21 = Cpk[1], a31 = Cpk[2];
    float a22 = Cpk[3], a32 = Cpk[4], a33 = Cpk[5];

    // ---- ssytd2 lower: one reflector annihilating a31 ----
    float d[3], e[2], tau1, v3;
    {
        float xnorm = fabsf(a31);
        if (xnorm == 0.f) { tau1 = 0.f; v3 = 0.f; e[0] = a21; }
        else {
            float beta = -copysignf(f_slapy2(a21, xnorm), a21);
            tau1 = __fdiv_rn(beta - a21, beta);
            v3 = a31 * __fdiv_rn(1.f, a21 - beta);
            e[0] = beta;
        }
        if (tau1 != 0.f) {
            float x1 = tau1 * (a22 + a32 * v3);   // x = tau*A22*v, v=[1,v3]
            float x2 = tau1 * (a32 + a33 * v3);
            float al = -0.5f * tau1 * (x1 + x2 * v3);
            float w1 = x1 + al;
            float w2 = x2 + al * v3;
            a22 = a22 - w1 - w1;                  // A -= v w^T + w v^T
            a32 = a32 - v3 * w1 - w2;
            a33 = a33 - v3 * w2 - v3 * w2;
        }
        d[0] = a11; d[1] = a22; d[2] = a33; e[1] = a32;
    }

    // ---- ssteqr('I', n=3) ----
    float Z[3][3] = {{1.f,0.f,0.f},{0.f,1.f,0.f},{0.f,0.f,1.f}};
    const float eps    = 5.9604645e-08f;   // slamch('E') for IEEE single
    const float eps2   = eps * eps;
    const float safmin = 1.1754944e-38f;
    const int   nmaxit = 90;               // 3 * 30
    int jtot = 0, l1 = 1;
    float wc[2], ws[2];

    for (;;) {                                       // label 10
        if (l1 > 3) break;
        if (l1 > 1) e[l1 - 2] = 0.f;
        int m = 3;
        if (l1 <= 2) {
            for (int mm = l1; mm <= 2; mm++) {
                float tst = fabsf(e[mm - 1]);
                if (tst == 0.f) { m = mm; break; }
                if (tst <= (__fsqrt_rn(fabsf(d[mm - 1])) *
                            __fsqrt_rn(fabsf(d[mm]))) * eps) {
                    e[mm - 1] = 0.f; m = mm; break;
                }
            }
        }
        int l = l1, lsv = l, lend = m, lendsv = lend;
        l1 = m + 1;
        if (lend == l) continue;
        float anorm = 0.f;
        for (int i = l; i <= lend; i++)     anorm = fmaxf(anorm, fabsf(d[i - 1]));
        for (int i = l; i <= lend - 1; i++) anorm = fmaxf(anorm, fabsf(e[i - 1]));
        if (anorm == 0.f) continue;
        if (fabsf(d[lend - 1]) < fabsf(d[l - 1])) { lend = lsv; l = lendsv; }

        if (lend > l) {
            // ================= QL iteration =================
            for (;;) {                                // label 40
                int m2 = lend;
                if (l != lend) {
                    for (int mm = l; mm <= lend - 1; mm++) {
                        float tst = e[mm - 1] * e[mm - 1];
                        if (tst <= (eps2 * fabsf(d[mm - 1])) * fabsf(d[mm]) + safmin) {
                            m2 = mm; break;
                        }
                    }
                }
                if (m2 < lend) e[m2 - 1] = 0.f;
                float p = d[l - 1];
                if (m2 == l) {                        // eigenvalue found
                    d[l - 1] = p; l++;
                    if (l <= lend) continue;
                    break;
                }
                if (m2 == l + 1) {                    // 2x2 deflation
                    float rt1, rt2, c2, s2;
                    f_slaev2(d[l - 1], e[l - 1], d[l], rt1, rt2, c2, s2);
                    #pragma unroll
                    for (int i = 0; i < 3; i++) {     // slasr 'R','V','B', 2 cols (l,l+1)
                        float t = Z[i][l];
                        Z[i][l]     = c2 * t - s2 * Z[i][l - 1];
                        Z[i][l - 1] = s2 * t + c2 * Z[i][l - 1];
                    }
                    d[l - 1] = rt1; d[l] = rt2; e[l - 1] = 0.f;
                    l += 2;
                    if (l <= lend) continue;
                    break;
                }
                if (jtot == nmaxit) break;
                jtot++;
                float g = __fdiv_rn(d[l] - p, 2.f * e[l - 1]);
                float r = f_slapy2(g, 1.f);
                g = d[m2 - 1] - p + __fdiv_rn(e[l - 1], g + copysignf(r, g));
                float sv = 1.f, cv = 1.f;
                p = 0.f;
                for (int i = m2 - 1; i >= l; i--) {
                    float f = sv * e[i - 1];
                    float b = cv * e[i - 1];
                    f_slartg(g, f, cv, sv, r);
                    if (i != m2 - 1) e[i] = r;
                    g = d[i] - p;
                    r = (d[i - 1] - g) * sv + 2.f * cv * b;
                    p = sv * r;
                    d[i] = g + p;
                    g = cv * r - b;
                    wc[i - 1] = cv; ws[i - 1] = -sv;
                }
                int mm = m2 - l + 1;                  // slasr 'R','V','B'
                for (int j = mm - 1; j >= 1; j--) {
                    float cc = wc[l + j - 2], ssv = ws[l + j - 2];
                    #pragma unroll
                    for (int i = 0; i < 3; i++) {
                        float t = Z[i][l + j - 1];
                        Z[i][l + j - 1] = cc * t - ssv * Z[i][l + j - 2];
                        Z[i][l + j - 2] = ssv * t + cc * Z[i][l + j - 2];
                    }
                }
                d[l - 1] -= p;
                e[l - 1] = g;
            }
        } else {
            // ================= QR iteration =================
            for (;;) {                                // label 90
                int m2 = lend;
                if (l != lend) {
                    for (int mm = l; mm >= lend + 1; mm--) {
                        float tst = e[mm - 2] * e[mm - 2];
                        if (tst <= (eps2 * fabsf(d[mm - 1])) * fabsf(d[mm - 2]) + safmin) {
                            m2 = mm; break;
                        }
                    }
                }
                if (m2 > lend) e[m2 - 2] = 0.f;
                float p = d[l - 1];
                if (m2 == l) {
                    d[l - 1] = p; l--;
                    if (l >= lend) continue;
                    break;
                }
                if (m2 == l - 1) {
                    float rt1, rt2, c2, s2;
                    f_slaev2(d[l - 2], e[l - 2], d[l - 1], rt1, rt2, c2, s2);
                    #pragma unroll
                    for (int i = 0; i < 3; i++) {     // slasr 'R','V','F', 2 cols (l-1,l)
                        float t = Z[i][l - 1];
                        Z[i][l - 1] = c2 * t - s2 * Z[i][l - 2];
                        Z[i][l - 2] = s2 * t + c2 * Z[i][l - 2];
                    }
                    d[l - 2] = rt1; d[l - 1] = rt2; e[l - 2] = 0.f;
                    l -= 2;
                    if (l >= lend) continue;
                    break;
                }
                if (jtot == nmaxit) break;
                jtot++;
                float g = __fdiv_rn(d[l - 2] - p, 2.f * e[l - 2]);
                float r = f_slapy2(g, 1.f);
                g = d[m2 - 1] - p + __fdiv_rn(e[l - 2], g + copysignf(r, g));
                float sv = 1.f, cv = 1.f;
                p = 0.f;
                for (int i = m2; i <= l - 1; i++) {
                    float f = sv * e[i - 1];
                    float b = cv * e[i - 1];
                    f_slartg(g, f, cv, sv, r);
                    if (i != m2) e[i - 2] = r;
                    g = d[i - 1] - p;
                    r = (d[i] - g) * sv + 2.f * cv * b;
                    p = sv * r;
                    d[i - 1] = g + p;
                    g = cv * r - b;
                    wc[i - 1] = cv; ws[i - 1] = sv;
                }
                int mm = l - m2 + 1;                  // slasr 'R','V','F'
                for (int j = 1; j <= mm - 1; j++) {
                    float cc = wc[m2 + j - 2], ssv = ws[m2 + j - 2];
                    #pragma unroll
                    for (int i = 0; i < 3; i++) {
                        float t = Z[i][m2 + j - 1];
                        Z[i][m2 + j - 1] = cc * t - ssv * Z[i][m2 + j - 2];
                        Z[i][m2 + j - 2] = ssv * t + cc * Z[i][m2 + j - 2];
                    }
                }
                d[l - 1] -= p;
                e[l - 2] = g;
            }
        }
    }

    // ---- selection sort ascending (LAPACK convention: min swaps) ----
    for (int ii = 2; ii <= 3; ii++) {
        int i = ii - 1, k = i;
        float p = d[i - 1];
        for (int j = ii; j <= 3; j++)
            if (d[j - 1] < p) { k = j; p = d[j - 1]; }
        if (k != i) {
            d[k - 1] = d[i - 1]; d[i - 1] = p;
            #pragma unroll
            for (int r2 = 0; r2 < 3; r2++) {
                float t = Z[r2][i - 1]; Z[r2][i - 1] = Z[r2][k - 1]; Z[r2][k - 1] = t;
            }
        }
    }

    // ---- sormtr: Z = H1 * Z (H1 acts on rows 1,2) ----
    if (tau1 != 0.f) {
        #pragma unroll
        for (int j = 0; j < 3; j++) {
            float t = Z[1][j] + v3 * Z[2][j];
            Z[1][j] -= tau1 * t;
            Z[2][j] -= tau1 * v3 * t;
        }
    }

    zv[0] = Z[0][0]; zv[1] = Z[1][0]; zv[2] = Z[2][0];   // smallest eigval
    xv[0] = Z[0][2]; xv[1] = Z[1][2]; xv[2] = Z[2][2];   // largest eigval
}

// ------------------------------- main kernel -------------------------------
// 256 threads / 32 groups per block. Phase1: warp w handles groups 4w..4w+3.
// Phase2: warp 0, one eigensolve PER LANE. Phase3: warp w finishes its groups.

constexpr int GPB = 32;   // groups per block

__global__ __launch_bounds__(256) void lrf_kernel(
    const float* __restrict__ nb, float* __restrict__ out)
{
    const int wib  = threadIdx.x >> 5;
    const int lane = threadIdx.x & 31;
    const int gbase = blockIdx.x * GPB;

    __shared__ float stage[8][192];
    __shared__ float scov[GPB][7];   // stride 7 -> conflict-free for lane==group
    __shared__ float svec[GPB][7];   // z(3), x(3)

    // each lane keeps its 2 points for this warp's 4 groups in registers
    float P0x[4], P0y[4], P0z[4], P1x[4], P1y[4], P1z[4];

    // ---------------- phase 1: load + covariance, 4 groups per warp --------
    #pragma unroll
    for (int u = 0; u < 4; u++) {
        const int gl = wib * 4 + u;
        const float* src = nb + (size_t)(gbase + gl) * 192;
        #pragma unroll
        for (int k = 0; k < 6; k++)
            stage[wib][lane + 32 * k] = src[lane + 32 * k];
        __syncwarp();

        const int o = lane * 6;
        const float p0x = stage[wib][o + 0], p0y = stage[wib][o + 1], p0z = stage[wib][o + 2];
        const float p1x = stage[wib][o + 3], p1y = stage[wib][o + 4], p1z = stage[wib][o + 5];
        P0x[u] = p0x; P0y[u] = p0y; P0z[u] = p0z;
        P1x[u] = p1x; P1y[u] = p1y; P1z[u] = p1z;
        __syncwarp();   // stage reads done before next iteration overwrites

        // weights exactly as reference: w = (max_norm - norm) / (sum + 1e-6)
        const float n0 = __fsqrt_rn(p0x * p0x + p0y * p0y + p0z * p0z);
        const float n1 = __fsqrt_rn(p1x * p1x + p1y * p1y + p1z * p1z);
        float mx = fmaxf(n0, n1);
        #pragma unroll
        for (int dd = 16; dd; dd >>= 1)
            mx = fmaxf(mx, __shfl_xor_sync(0xffffffffu, mx, dd));
        const float w0 = mx - n0, w1 = mx - n1;
        float swt = w0 + w1;
        #pragma unroll
        for (int dd = 16; dd; dd >>= 1)
            swt += __shfl_xor_sync(0xffffffffu, swt, dd);
        const float denom = swt + 1e-6f;
        const float q0 = __fdiv_rn(w0, denom);
        const float q1 = __fdiv_rn(w1, denom);

        // covariance over scaled_pos = 100*pos, term = (w*sp_k)*sp_l
        const float s0x = 100.f * p0x, s0y = 100.f * p0y, s0z = 100.f * p0z;
        const float s1x = 100.f * p1x, s1y = 100.f * p1y, s1z = 100.f * p1z;
        float cxx = (q0 * s0x) * s0x + (q1 * s1x) * s1x;
        float cxy = (q0 * s0y) * s0x + (q1 * s1y) * s1x;   // C[1][0]
        float cxz = (q0 * s0z) * s0x + (q1 * s1z) * s1x;   // C[2][0]
        float cyy = (q0 * s0y) * s0y + (q1 * s1y) * s1y;
        float cyz = (q0 * s0z) * s0y + (q1 * s1z) * s1y;   // C[2][1]
        float czz = (q0 * s0z) * s0z + (q1 * s1z) * s1z;
        #pragma unroll
        for (int dd = 16; dd; dd >>= 1) {
            cxx += __shfl_xor_sync(0xffffffffu, cxx, dd);
            cxy += __shfl_xor_sync(0xffffffffu, cxy, dd);
            cxz += __shfl_xor_sync(0xffffffffu, cxz, dd);
            cyy += __shfl_xor_sync(0xffffffffu, cyy, dd);
            cyz += __shfl_xor_sync(0xffffffffu, cyz, dd);
            czz += __shfl_xor_sync(0xffffffffu, czz, dd);
        }
        if (lane == 0) {
            scov[gl][0] = cxx; scov[gl][1] = cxy; scov[gl][2] = cxz;
            scov[gl][3] = cyy; scov[gl][4] = cyz; scov[gl][5] = czz;
        }
    }
    __syncthreads();

    // ---------------- phase 2: 32 lane-parallel eigensolves (warp 0) -------
    if (threadIdx.x < GPB) {
        float Cpk[6] = {scov[threadIdx.x][0], scov[threadIdx.x][1],
                        scov[threadIdx.x][2], scov[threadIdx.x][3],
                        scov[threadIdx.x][4], scov[threadIdx.x][5]};
        float zv[3], xv[3];
        eigh3_lapack(Cpk, zv, xv);
        svec[threadIdx.x][0] = zv[0]; svec[threadIdx.x][1] = zv[1];
        svec[threadIdx.x][2] = zv[2]; svec[threadIdx.x][3] = xv[0];
        svec[threadIdx.x][4] = xv[1]; svec[threadIdx.x][5] = xv[2];
    }
    __syncthreads();

    // ---------------- phase 3: disambiguate + rotate + store ---------------
    #pragma unroll
    for (int u = 0; u < 4; u++) {
        const int gl = wib * 4 + u;
        const int g  = gbase + gl;
        float zx = svec[gl][0], zy = svec[gl][1], zz = svec[gl][2];
        float xx = svec[gl][3], xy = svec[gl][4], xz = svec[gl][5];
        const float p0x = P0x[u], p0y = P0y[u], p0z = P0z[u];
        const float p1x = P1x[u], p1y = P1y[u], p1z = P1z[u];

        // flip if #(pos . v > 0) < 32 ; tie keeps eigh's sign
        {
            float pj0 = zx * p0x + zy * p0y + zz * p0z;
            float pj1 = zx * p1x + zy * p1y + zz * p1z;
            int npos = __popc(__ballot_sync(0xffffffffu, pj0 > 0.f)) +
                       __popc(__ballot_sync(0xffffffffu, pj1 > 0.f));
            if (npos < 32) { zx = -zx; zy = -zy; zz = -zz; }
        }
        {
            float pj0 = xx * p0x + xy * p0y + xz * p0z;
            float pj1 = xx * p1x + xy * p1y + xz * p1z;
            int npos = __popc(__ballot_sync(0xffffffffu, pj0 > 0.f)) +
                       __popc(__ballot_sync(0xffffffffu, pj1 > 0.f));
            if (npos < 32) { xx = -xx; xy = -xy; xz = -xz; }
        }

        // y = z x x
        const float yx = zy * xz - zz * xy;
        const float yy = zz * xx - zx * xz;
        const float yz = zx * xy - zy * xx;

        // lrfs: rows = component, cols = (z, y, x)
        if (lane == 0) {
            float* L = out + ROT_ELEMS + (size_t)g * 9;
            L[0] = zx; L[1] = yx; L[2] = xx;
            L[3] = zy; L[4] = yy; L[5] = xy;
            L[6] = zz; L[7] = yz; L[8] = xz;
        }

        // rot_neighbor = pos @ lrfs, staged through smem for coalesced stores
        const int o = lane * 6;
        stage[wib][o + 0] = p0x * zx + p0y * zy + p0z * zz;
        stage[wib][o + 1] = p0x * yx + p0y * yy + p0z * yz;
        stage[wib][o + 2] = p0x * xx + p0y * xy + p0z * xz;
        stage[wib][o + 3] = p1x * zx + p1y * zy + p1z * zz;
        stage[wib][o + 4] = p1x * yx + p1y * yy + p1z * yz;
        stage[wib][o + 5] = p1x * xx + p1y * xy + p1z * xz;
        __syncwarp();

        float* dst = out + (size_t)g * 192;
        #pragma unroll
        for (int k = 0; k < 6; k++)
            dst[lane + 32 * k] = stage[wib][lane + 32 * k];
        __syncwarp();   // stores read stage before next iteration overwrites
    }
}

extern "C" void kernel_launch(void* const* d_in, const int* in_sizes, int n_in,
                              void* d_out, int out_size) {
    const float* neighbor = (const float*)d_in[0];
    float* out = (float*)d_out;
    lrf_kernel<<<NG / GPB, 256>>>(neighbor, out);
}